// round 7
// baseline (speedup 1.0000x reference)
#include <cuda_runtime.h>
#include <math.h>

#define TSEQ    2048
#define HID     128
#define NLAYERS 5
#define BATCH   256
#define WPAD    132   // padded row length (floats) for transposed weights in smem

// Scratch for x-projections of one layer: [B*T, 384] fp32 (r|z|h gates + bias)
static __device__ float g_xproj[(size_t)BATCH * TSEQ * 384];

// ---------------- f32x2 packed-FMA helpers (sm_100+) ----------------
__device__ __forceinline__ unsigned long long ffma2(unsigned long long a,
                                                    unsigned long long b,
                                                    unsigned long long c) {
    unsigned long long d;
    asm("fma.rn.f32x2 %0, %1, %2, %3;" : "=l"(d) : "l"(a), "l"(b), "l"(c));
    return d;
}
__device__ __forceinline__ float flo(unsigned long long v) {
    return __uint_as_float((unsigned int)v);
}
__device__ __forceinline__ float fhi(unsigned long long v) {
    return __uint_as_float((unsigned int)(v >> 32));
}
__device__ __forceinline__ float sigmoidf_(float x) {
    return 1.0f / (1.0f + expf(-x));
}

// =====================================================================
// Kernel 1: x-projection GEMM for one layer.
//   xout[row, j] = sum_k xin[row,k] * Wx{r|z|h}[k, j%128] + bias[j]
//   rows = B*T (row = b*T + t), j in [0,384): 0..127 r, 128..255 z, 256..383 h
// W held transposed in smem: WT[j][k], row pad WPAD. X tile 32 rows in smem.
// Each thread: 4 rows x 12 cols, f32x2 packed over k (even/odd partial sums).
// =====================================================================
#define XPROJ_SMEM ((384 * WPAD + 32 * 128 + 384) * 4)

__global__ void __launch_bounds__(256, 1)
xproj_kernel(const float* __restrict__ xin,
             const float* __restrict__ Wxr, const float* __restrict__ Wxz,
             const float* __restrict__ Wxh,
             const float* __restrict__ br, const float* __restrict__ bz,
             const float* __restrict__ bh,
             int nrows) {
    extern __shared__ float sm[];
    float* WT = sm;                       // [384][WPAD]
    float* Xs = sm + 384 * WPAD;          // [32][128]
    float* bs = Xs + 32 * 128;            // [384]

    const int tid = threadIdx.x;

    // Load weights transposed: WT[j][k] = W_sel[k*128 + (j&127)]
    for (int idx = tid; idx < 384 * 128; idx += 256) {
        int k = idx / 384, j = idx % 384;
        const float* src = (j < 128) ? Wxr : (j < 256) ? Wxz : Wxh;
        WT[j * WPAD + k] = src[k * 128 + (j & 127)];
    }
    for (int i = tid; i < 384; i += 256)
        bs[i] = (i < 128) ? br[i] : (i < 256) ? bz[i - 128] : bh[i - 256];
    __syncthreads();

    const int tc = tid & 31;   // column group
    const int tr = tid >> 5;   // row group (0..7), 4 rows each
    const int ntiles = nrows / 32;

    for (int tile = blockIdx.x; tile < ntiles; tile += gridDim.x) {
        __syncthreads();  // previous tile's compute done before Xs overwrite
        const long row0 = (long)tile * 32;
        // Load 32x128 X tile (16 KB), coalesced float4
        for (int i = tid; i < 1024; i += 256)
            ((float4*)Xs)[i] = ((const float4*)xin)[row0 * 32 + i];
        __syncthreads();

        unsigned long long acc[4][12];
#pragma unroll
        for (int r = 0; r < 4; r++)
#pragma unroll
            for (int c = 0; c < 12; c++) acc[r][c] = 0ull;

        const float* xr = Xs + (tr * 4) * 128;
#pragma unroll 4
        for (int k = 0; k < 128; k += 4) {
            ulonglong2 x0 = *(const ulonglong2*)(xr + k);
            ulonglong2 x1 = *(const ulonglong2*)(xr + 128 + k);
            ulonglong2 x2 = *(const ulonglong2*)(xr + 256 + k);
            ulonglong2 x3 = *(const ulonglong2*)(xr + 384 + k);
#pragma unroll
            for (int jj = 0; jj < 12; jj++) {
                const int c = tc + (jj << 5);
                ulonglong2 w = *(const ulonglong2*)(WT + c * WPAD + k);
                acc[0][jj] = ffma2(x0.x, w.x, acc[0][jj]);
                acc[0][jj] = ffma2(x0.y, w.y, acc[0][jj]);
                acc[1][jj] = ffma2(x1.x, w.x, acc[1][jj]);
                acc[1][jj] = ffma2(x1.y, w.y, acc[1][jj]);
                acc[2][jj] = ffma2(x2.x, w.x, acc[2][jj]);
                acc[2][jj] = ffma2(x2.y, w.y, acc[2][jj]);
                acc[3][jj] = ffma2(x3.x, w.x, acc[3][jj]);
                acc[3][jj] = ffma2(x3.y, w.y, acc[3][jj]);
            }
        }

#pragma unroll
        for (int r = 0; r < 4; r++) {
            const long row = row0 + tr * 4 + r;
            float* orow = g_xproj + row * 384;
#pragma unroll
            for (int jj = 0; jj < 12; jj++) {
                const int c = tc + (jj << 5);
                orow[c] = flo(acc[r][jj]) + fhi(acc[r][jj]) + bs[c];
            }
        }
    }
}

// =====================================================================
// Kernel 2: recurrence for one layer. 128 persistent CTAs, each owns 2
// batch rows; no inter-CTA communication. Recurrent weights transposed
// in smem as WT[j][k] (j: 0..127 Whr cols, 128..255 Whz, 256..383 Whh).
// Per step:
//   phase1 (256 thr): u = h @ [Whr|Whz] + xproj; R,Z = sigmoid; rh = R*h
//   phase2 (thr<128): c = (R*h) @ Whh + xproj_h; ht = tanh(c);
//                     h = Z*ht + (1-Z)*h; store to out.
//          (thr>=128): prefetch next step's xproj into double buffer.
// =====================================================================
#define REC_SMEM ((384 * WPAD + 3 * 256 + 2 * 768) * 4)

__global__ void __launch_bounds__(256, 1)
gru_rec_kernel(const float* __restrict__ Whr, const float* __restrict__ Whz,
               const float* __restrict__ Whh,
               float* __restrict__ out, int T) {
    extern __shared__ float sm[];
    float* WT  = sm;                    // [384][WPAD]
    float* hs  = sm + 384 * WPAD;       // [2][128]
    float* rhs = hs + 256;              // [2][128]  (R * h)
    float* zs  = rhs + 256;             // [2][128]  (Z)
    float* xp  = zs + 256;              // [2][768]  xproj double buffer

    const int tid = threadIdx.x;
    const long b0 = (long)blockIdx.x * 2;
    const float* __restrict__ xq = g_xproj;

    for (int idx = tid; idx < 384 * 128; idx += 256) {
        int k = idx / 384, j = idx % 384;
        const float* src = (j < 128) ? Whr : (j < 256) ? Whz : Whh;
        WT[j * WPAD + k] = src[k * 128 + (j & 127)];
    }
    hs[tid] = 0.0f;  // 256 threads cover [2][128]
    // preload xproj for t = 0 into buffer 0
    for (int i = tid; i < 768; i += 256) {
        int r = i / 384, c = i % 384;
        xp[i] = xq[((b0 + r) * (long)T + 0) * 384 + c];
    }
    __syncthreads();

    const float* w1 = WT + tid * WPAD;

    for (int t = 0; t < T; t++) {
        const int cur = (t & 1) * 768;

        // ---- phase 1: gate pre-activations for col tid, both rows ----
        unsigned long long a0 = 0ull, a1 = 0ull;
#pragma unroll
        for (int k = 0; k < 128; k += 4) {
            ulonglong2 w  = *(const ulonglong2*)(w1 + k);
            ulonglong2 h0 = *(const ulonglong2*)(hs + k);
            ulonglong2 h1 = *(const ulonglong2*)(hs + 128 + k);
            a0 = ffma2(h0.x, w.x, a0);
            a0 = ffma2(h0.y, w.y, a0);
            a1 = ffma2(h1.x, w.x, a1);
            a1 = ffma2(h1.y, w.y, a1);
        }
        const float u0 = flo(a0) + fhi(a0) + xp[cur + tid];
        const float u1 = flo(a1) + fhi(a1) + xp[cur + 384 + tid];
        const float s0 = sigmoidf_(u0);
        const float s1 = sigmoidf_(u1);
        if (tid < 128) {              // r-gate: store R * h
            rhs[tid]       = s0 * hs[tid];
            rhs[128 + tid] = s1 * hs[128 + tid];
        } else {                      // z-gate: store Z
            const int c = tid - 128;
            zs[c]       = s0;
            zs[128 + c] = s1;
        }
        __syncthreads();

        // ---- phase 2 ----
        if (tid < 128) {
            const float* w2 = WT + (256 + tid) * WPAD;
            unsigned long long c0 = 0ull, c1 = 0ull;
#pragma unroll
            for (int k = 0; k < 128; k += 4) {
                ulonglong2 w  = *(const ulonglong2*)(w2 + k);
                ulonglong2 r0 = *(const ulonglong2*)(rhs + k);
                ulonglong2 r1 = *(const ulonglong2*)(rhs + 128 + k);
                c0 = ffma2(r0.x, w.x, c0);
                c0 = ffma2(r0.y, w.y, c0);
                c1 = ffma2(r1.x, w.x, c1);
                c1 = ffma2(r1.y, w.y, c1);
            }
            const float uh0 = flo(c0) + fhi(c0) + xp[cur + 256 + tid];
            const float uh1 = flo(c1) + fhi(c1) + xp[cur + 640 + tid];
            const float th0 = tanhf(uh0);
            const float th1 = tanhf(uh1);
            const float z0 = zs[tid],      z1 = zs[128 + tid];
            const float hp0 = hs[tid],     hp1 = hs[128 + tid];
            const float hn0 = z0 * th0 + (1.0f - z0) * hp0;
            const float hn1 = z1 * th1 + (1.0f - z1) * hp1;
            hs[tid]       = hn0;
            hs[128 + tid] = hn1;
            out[(b0 * T + t) * 128 + tid]       = hn0;
            out[((b0 + 1) * T + t) * 128 + tid] = hn1;
        } else if (t + 1 < T) {
            // prefetch next step's xproj into the other buffer
            const int i = tid - 128;
            const int nxt = ((t + 1) & 1) * 768;
#pragma unroll
            for (int q = 0; q < 6; q++) {
                const int idx = i + (q << 7);
                const int r = idx / 384, c = idx % 384;
                xp[nxt + idx] = xq[((b0 + r) * (long)T + (t + 1)) * 384 + c];
            }
        }
        __syncthreads();
    }
}

// =====================================================================
extern "C" void kernel_launch(void* const* d_in, const int* in_sizes, int n_in,
                              void* d_out, int out_size) {
    const float* inputs = (const float*)d_in[0];
    const float* Whr = (const float*)d_in[1];
    const float* Wxr = (const float*)d_in[2];
    const float* br  = (const float*)d_in[3];
    const float* Whz = (const float*)d_in[4];
    const float* Wxz = (const float*)d_in[5];
    const float* bz  = (const float*)d_in[6];
    const float* Whh = (const float*)d_in[7];
    const float* Wxh = (const float*)d_in[8];
    const float* bh  = (const float*)d_in[9];
    float* out = (float*)d_out;

    cudaFuncSetAttribute(xproj_kernel,
                         cudaFuncAttributeMaxDynamicSharedMemorySize, XPROJ_SMEM);
    cudaFuncSetAttribute(gru_rec_kernel,
                         cudaFuncAttributeMaxDynamicSharedMemorySize, REC_SMEM);

    const int WSTRIDE = HID * HID;
    for (int l = 0; l < NLAYERS; l++) {
        const float* xin = (l == 0) ? inputs : out;
        xproj_kernel<<<148, 256, XPROJ_SMEM>>>(
            xin,
            Wxr + (size_t)l * WSTRIDE, Wxz + (size_t)l * WSTRIDE,
            Wxh + (size_t)l * WSTRIDE,
            br + (size_t)l * HID, bz + (size_t)l * HID, bh + (size_t)l * HID,
            BATCH * TSEQ);
        gru_rec_kernel<<<BATCH / 2, 256, REC_SMEM>>>(
            Whr + (size_t)l * WSTRIDE, Whz + (size_t)l * WSTRIDE,
            Whh + (size_t)l * WSTRIDE,
            out, TSEQ);
    }
}

// round 14
// speedup vs baseline: 1.3400x; 1.3400x over previous
#include <cuda_runtime.h>
#include <math.h>

#define TSEQ    2048
#define HID     128
#define NLAYERS 5
#define BATCH   256
#define WPAD    132   // padded row length (floats) for transposed weights in smem

// Scratch for x-projections of one layer: [B*T, 384] fp32 (r|z|h gates + bias)
static __device__ float g_xproj[(size_t)BATCH * TSEQ * 384];

// ---------------- f32x2 packed-FMA helpers (sm_100+) ----------------
__device__ __forceinline__ unsigned long long ffma2(unsigned long long a,
                                                    unsigned long long b,
                                                    unsigned long long c) {
    unsigned long long d;
    asm("fma.rn.f32x2 %0, %1, %2, %3;" : "=l"(d) : "l"(a), "l"(b), "l"(c));
    return d;
}
__device__ __forceinline__ unsigned long long packf2(float lo, float hi) {
    unsigned long long d;
    asm("mov.b64 %0, {%1, %2};" : "=l"(d) : "f"(lo), "f"(hi));
    return d;
}
__device__ __forceinline__ float flo(unsigned long long v) {
    return __uint_as_float((unsigned int)v);
}
__device__ __forceinline__ float fhi(unsigned long long v) {
    return __uint_as_float((unsigned int)(v >> 32));
}
// Accurate activations (fast variants caused 5e-3 rel_err via cancellation
// in 1-2/(e^{2x}+1) at small |x|; gate inputs here ARE small).
__device__ __forceinline__ float sigmoidf_(float x) {
    return 1.0f / (1.0f + expf(-x));
}

// =====================================================================
// Kernel 1: x-projection GEMM for one layer.
//   g_xproj[row, j] = sum_k xin[row,k] * Wx{r|z|h}[k, j%128] + bias[j]
// W transposed in smem WT[j][k] (pad WPAD -> conflict-free LDS.128).
// Thread tile: 8 rows x 6 cols (w column reused by 8 rows -> LDS < FFMA).
// =====================================================================
#define XPROJ_SMEM ((384 * WPAD + 32 * 128 + 384) * 4)

__global__ void __launch_bounds__(256, 1)
xproj_kernel(const float* __restrict__ xin,
             const float* __restrict__ Wxr, const float* __restrict__ Wxz,
             const float* __restrict__ Wxh,
             const float* __restrict__ br, const float* __restrict__ bz,
             const float* __restrict__ bh,
             int nrows) {
    extern __shared__ float sm[];
    float* WT = sm;                       // [384][WPAD]
    float* Xs = sm + 384 * WPAD;          // [32][128]
    float* bs = Xs + 32 * 128;            // [384]

    const int tid = threadIdx.x;

    for (int idx = tid; idx < 384 * 128; idx += 256) {
        int k = idx / 384, j = idx % 384;
        const float* src = (j < 128) ? Wxr : (j < 256) ? Wxz : Wxh;
        WT[j * WPAD + k] = src[k * 128 + (j & 127)];
    }
    for (int i = tid; i < 384; i += 256)
        bs[i] = (i < 128) ? br[i] : (i < 256) ? bz[i - 128] : bh[i - 256];
    __syncthreads();

    const int tc = tid & 63;   // column group: cols tc + jj*64, jj<6
    const int tr = tid >> 6;   // row group (0..3), 8 rows each
    const int ntiles = nrows / 32;

    for (int tile = blockIdx.x; tile < ntiles; tile += gridDim.x) {
        __syncthreads();
        const long row0 = (long)tile * 32;
        for (int i = tid; i < 1024; i += 256)
            ((float4*)Xs)[i] = ((const float4*)xin)[row0 * 32 + i];
        __syncthreads();

        unsigned long long acc[8][6];
#pragma unroll
        for (int r = 0; r < 8; r++)
#pragma unroll
            for (int c = 0; c < 6; c++) acc[r][c] = 0ull;

        const float* xr = Xs + (tr * 8) * 128;
#pragma unroll 2
        for (int k = 0; k < 128; k += 4) {
            ulonglong2 xv[8];
#pragma unroll
            for (int r = 0; r < 8; r++)
                xv[r] = *(const ulonglong2*)(xr + r * 128 + k);
#pragma unroll
            for (int jj = 0; jj < 6; jj++) {
                const int c = tc + (jj << 6);
                ulonglong2 w = *(const ulonglong2*)(WT + c * WPAD + k);
#pragma unroll
                for (int r = 0; r < 8; r++) {
                    acc[r][jj] = ffma2(xv[r].x, w.x, acc[r][jj]);
                    acc[r][jj] = ffma2(xv[r].y, w.y, acc[r][jj]);
                }
            }
        }

#pragma unroll
        for (int r = 0; r < 8; r++) {
            const long row = row0 + tr * 8 + r;
            float* orow = g_xproj + row * 384;
#pragma unroll
            for (int jj = 0; jj < 6; jj++) {
                const int c = tc + (jj << 6);
                orow[c] = flo(acc[r][jj]) + fhi(acc[r][jj]) + bs[c];
            }
        }
    }
}

// =====================================================================
// Kernel 2: recurrence, weights RESIDENT IN REGISTERS.
// 128 CTAs x 256 threads, 2 batch rows per CTA, 1 CTA/SM.
// Thread t owns:
//   phase1: gate column g=t (t<128: Whr col t; else Whz col t-128),
//           full k, both rows.  w1p[64] packed f32x2 (128 regs).
//   phase2: Whh column c2=t&127, k-half kh=t>>7, both rows.
//           w2p[32] (64 regs). Partials combined through smem.
// Per step: P1 -> E1(sigmoid, write R*h / Z) -> bar -> P2(half dots)
//           -> bar -> E2(tanh, h update, store) -> bar.  Zero weight LDS.
// xproj operands prefetched one step ahead into registers (3 LDG/thread).
// =====================================================================
__global__ void __launch_bounds__(256, 1)
gru_rec_kernel(const float* __restrict__ Whr, const float* __restrict__ Whz,
               const float* __restrict__ Whh,
               float* __restrict__ out, int T) {
    __shared__ __align__(16) float hs[256];    // [2][128] hidden state
    __shared__ __align__(16) float rhs[256];   // [2][128] R*h
    __shared__ __align__(16) float zs[256];    // [2][128] Z
    __shared__ __align__(16) float part[512];  // [2 khalf][2 row][128 col]

    const int tid = threadIdx.x;
    const long b0 = (long)blockIdx.x * 2;
    const float* __restrict__ xq = g_xproj;

    // ---- phase1 weights into registers (coalesced across lanes) ----
    const int g  = tid;
    const int c1 = g & 127;
    const float* W1 = (g < 128) ? Whr : Whz;
    unsigned long long w1p[64];
#pragma unroll
    for (int i = 0; i < 64; i++)
        w1p[i] = packf2(W1[(2 * i) * 128 + c1], W1[(2 * i + 1) * 128 + c1]);

    // ---- phase2 weights ----
    const int c2 = tid & 127;
    const int kh = tid >> 7;   // 0 or 1
    unsigned long long w2p[32];
#pragma unroll
    for (int i = 0; i < 32; i++) {
        int k = kh * 64 + 2 * i;
        w2p[i] = packf2(Whh[k * 128 + c2], Whh[(k + 1) * 128 + c2]);
    }

    hs[tid] = 0.0f;
    __syncthreads();

    // xproj pointers + prefetch for t=0
    const float* xg0p = xq + (size_t)(b0)     * T * 384 + g;         // row0 gate
    const float* xg1p = xq + (size_t)(b0 + 1) * T * 384 + g;         // row1 gate
    const float* xhp  = xq + (size_t)(b0 + kh) * T * 384 + 256 + c2; // h-gate (row=kh)
    float xg0 = xg0p[0], xg1 = xg1p[0], xh = xhp[0];

    for (int t = 0; t < T; t++) {
        const float cxg0 = xg0, cxg1 = xg1, cxh = xh;
        if (t + 1 < T) {   // prefetch next step (covers DRAM latency over the step)
            xg0 = xg0p[(t + 1) * 384];
            xg1 = xg1p[(t + 1) * 384];
            xh  = xhp[(t + 1) * 384];
        }

        // ---- phase 1: gate pre-activations, weights from registers ----
        unsigned long long a0 = 0ull, b0a = 0ull, a1 = 0ull, b1a = 0ull;
#pragma unroll
        for (int i = 0; i < 32; i++) {
            ulonglong2 h0 = *(const ulonglong2*)(hs + 4 * i);
            ulonglong2 h1 = *(const ulonglong2*)(hs + 128 + 4 * i);
            a0  = ffma2(h0.x, w1p[2 * i],     a0);
            b0a = ffma2(h0.y, w1p[2 * i + 1], b0a);
            a1  = ffma2(h1.x, w1p[2 * i],     a1);
            b1a = ffma2(h1.y, w1p[2 * i + 1], b1a);
        }
        const float u0 = flo(a0) + fhi(a0) + flo(b0a) + fhi(b0a) + cxg0;
        const float u1 = flo(a1) + fhi(a1) + flo(b1a) + fhi(b1a) + cxg1;
        const float s0 = sigmoidf_(u0);
        const float s1 = sigmoidf_(u1);
        if (g < 128) {                 // R gate: stage R*h
            rhs[c1]       = s0 * hs[c1];
            rhs[128 + c1] = s1 * hs[128 + c1];
        } else {                       // Z gate
            zs[c1]       = s0;
            zs[128 + c1] = s1;
        }
        __syncthreads();

        // ---- phase 2: (R*h) @ Whh, k-split half-dots ----
        unsigned long long p0 = 0ull, q0 = 0ull, p1 = 0ull, q1 = 0ull;
        const float* rbase = rhs + kh * 64;
#pragma unroll
        for (int i = 0; i < 16; i++) {
            ulonglong2 r0 = *(const ulonglong2*)(rbase + 4 * i);
            ulonglong2 r1 = *(const ulonglong2*)(rbase + 128 + 4 * i);
            p0 = ffma2(r0.x, w2p[2 * i],     p0);
            q0 = ffma2(r0.y, w2p[2 * i + 1], q0);
            p1 = ffma2(r1.x, w2p[2 * i],     p1);
            q1 = ffma2(r1.y, w2p[2 * i + 1], q1);
        }
        part[kh * 256 + c2]       = flo(p0) + fhi(p0) + flo(q0) + fhi(q0);
        part[kh * 256 + 128 + c2] = flo(p1) + fhi(p1) + flo(q1) + fhi(q1);
        __syncthreads();

        // ---- epilogue: thread t handles (row = kh, col = c2) ----
        {
            const float v  = part[kh * 128 + c2] + part[256 + kh * 128 + c2] + cxh;
            const float th = tanhf(v);
            const float z  = zs[kh * 128 + c2];
            const float hp = hs[kh * 128 + c2];
            const float hn = z * th + (1.0f - z) * hp;
            hs[kh * 128 + c2] = hn;
            out[(size_t)((b0 + kh) * T + t) * 128 + c2] = hn;
        }
        __syncthreads();
    }
}

// =====================================================================
extern "C" void kernel_launch(void* const* d_in, const int* in_sizes, int n_in,
                              void* d_out, int out_size) {
    const float* inputs = (const float*)d_in[0];
    const float* Whr = (const float*)d_in[1];
    const float* Wxr = (const float*)d_in[2];
    const float* br  = (const float*)d_in[3];
    const float* Whz = (const float*)d_in[4];
    const float* Wxz = (const float*)d_in[5];
    const float* bz  = (const float*)d_in[6];
    const float* Whh = (const float*)d_in[7];
    const float* Wxh = (const float*)d_in[8];
    const float* bh  = (const float*)d_in[9];
    float* out = (float*)d_out;

    cudaFuncSetAttribute(xproj_kernel,
                         cudaFuncAttributeMaxDynamicSharedMemorySize, XPROJ_SMEM);

    const int WSTRIDE = HID * HID;
    for (int l = 0; l < NLAYERS; l++) {
        const float* xin = (l == 0) ? inputs : out;
        xproj_kernel<<<148, 256, XPROJ_SMEM>>>(
            xin,
            Wxr + (size_t)l * WSTRIDE, Wxz + (size_t)l * WSTRIDE,
            Wxh + (size_t)l * WSTRIDE,
            br + (size_t)l * HID, bz + (size_t)l * HID, bh + (size_t)l * HID,
            BATCH * TSEQ);
        gru_rec_kernel<<<BATCH / 2, 256>>>(
            Whr + (size_t)l * WSTRIDE, Whz + (size_t)l * WSTRIDE,
            Whh + (size_t)l * WSTRIDE,
            out, TSEQ);
    }
}